// round 4
// baseline (speedup 1.0000x reference)
#include <cuda_runtime.h>
#include <cuda_bf16.h>
#include <cstdint>

#define T_DIM 512
#define B_DIM 128
#define E_DIM 256
#define U_DIM 256

// Scratch for xW[t][b][u]  (64 MB fp32 — L2-resident)
__device__ float g_xw[T_DIM * B_DIM * U_DIM];

// ---------------- helpers ----------------
__device__ __forceinline__ uint32_t smem_u32(const void* p) {
    uint32_t a;
    asm("{ .reg .u64 t; cvta.to.shared.u64 t, %1; cvt.u32.u64 %0, t; }" : "=r"(a) : "l"(p));
    return a;
}
__device__ __forceinline__ uint32_t packbf(float a, float b) {
    __nv_bfloat162 t = __floats2bfloat162_rn(a, b);   // .x -> low 16, .y -> high 16
    return *reinterpret_cast<uint32_t*>(&t);
}
__device__ __forceinline__ float blo(uint32_t v) { return __uint_as_float(v << 16); }

__device__ __forceinline__ void ldsm_x4(uint32_t* r, uint32_t addr) {
    asm volatile("ldmatrix.sync.aligned.m8n8.x4.shared.b16 {%0,%1,%2,%3}, [%4];"
                 : "=r"(r[0]), "=r"(r[1]), "=r"(r[2]), "=r"(r[3]) : "r"(addr));
}
__device__ __forceinline__ void ldsm_x2(uint32_t* r, uint32_t addr) {
    asm volatile("ldmatrix.sync.aligned.m8n8.x2.shared.b16 {%0,%1}, [%2];"
                 : "=r"(r[0]), "=r"(r[1]) : "r"(addr));
}
__device__ __forceinline__ void mma_bf16(float* c, const uint32_t* a, const uint32_t* b) {
    asm volatile("mma.sync.aligned.m16n8k16.row.col.f32.bf16.bf16.f32 "
                 "{%0,%1,%2,%3}, {%4,%5,%6,%7}, {%8,%9}, {%0,%1,%2,%3};"
                 : "+f"(c[0]), "+f"(c[1]), "+f"(c[2]), "+f"(c[3])
                 : "r"(a[0]), "r"(a[1]), "r"(a[2]), "r"(a[3]), "r"(b[0]), "r"(b[1]));
}

// ---------------- Kernel 1: xW[t][b][u] = emb[token(b,t)] . W[u] ----------------
// One CTA per timestep t (512 CTAs, 256 threads / 8 warps), bf16 HMMA.

static constexpr int APAD = 264;                     // bf16 elems per smem row
static constexpr int AS_OFF = 0;
static constexpr int BS_OFF = 128 * APAD * 2;        // 67584
static constexpr int XW_SMEM = BS_OFF + 256 * APAD * 2;  // 202752

__global__ void __launch_bounds__(256, 1)
xw_kernel(const int* __restrict__ sentence, const float* __restrict__ emb,
          const float* __restrict__ W) {
    extern __shared__ char smem[];
    const int tid = threadIdx.x, t = blockIdx.x;
    const int wid = tid >> 5, lane = tid & 31;
    const uint32_t sb = smem_u32(smem);

    // stage A (emb rows of this timestep's tokens)
    {
        const int sub = tid & 7;
        #pragma unroll
        for (int p = 0; p < 4; p++) {
            const int r = p * 32 + (tid >> 3);
            const int tok = sentence[r * T_DIM + t];
            const float4* src = reinterpret_cast<const float4*>(emb + (size_t)tok * E_DIM) + sub;
            char* dstrow = smem + AS_OFF + r * (APAD * 2);
            #pragma unroll
            for (int j = 0; j < 8; j++) {
                float4 v = src[j * 8];
                *reinterpret_cast<uint2*>(dstrow + (sub + j * 8) * 8) =
                    make_uint2(packbf(v.x, v.y), packbf(v.z, v.w));
            }
        }
    }
    // stage B (W rows)
    {
        const int sub = tid & 7;
        #pragma unroll
        for (int p = 0; p < 8; p++) {
            const int r = p * 32 + (tid >> 3);
            const float4* src = reinterpret_cast<const float4*>(W + (size_t)r * E_DIM) + sub;
            char* dstrow = smem + BS_OFF + r * (APAD * 2);
            #pragma unroll
            for (int j = 0; j < 8; j++) {
                float4 v = src[j * 8];
                *reinterpret_cast<uint2*>(dstrow + (sub + j * 8) * 8) =
                    make_uint2(packbf(v.x, v.y), packbf(v.z, v.w));
            }
        }
    }
    __syncthreads();

    const int m0 = wid * 16;
    float c[32][4];
    #pragma unroll
    for (int j = 0; j < 32; j++) { c[j][0] = c[j][1] = c[j][2] = c[j][3] = 0.f; }

    const uint32_t a_addr = sb + AS_OFF + (m0 + (lane & 15)) * (APAD * 2) + (lane >> 4) * 16;
    const uint32_t b_addr = sb + BS_OFF + (lane & 7) * (APAD * 2) + ((lane >> 3) & 1) * 16;

    for (int k = 0; k < 16; k++) {
        uint32_t a[4];
        ldsm_x4(a, a_addr + k * 32);
        #pragma unroll
        for (int j = 0; j < 32; j++) {
            uint32_t b[2];
            ldsm_x2(b, b_addr + j * 8 * (APAD * 2) + k * 32);
            mma_bf16(c[j], a, b);
        }
    }

    float* outp = g_xw + (size_t)t * (B_DIM * U_DIM);
    const int r0 = m0 + (lane >> 2), c0 = (lane & 3) * 2;
    #pragma unroll
    for (int j = 0; j < 32; j++) {
        const int col = j * 8 + c0;
        *reinterpret_cast<float2*>(outp + r0 * U_DIM + col)       = make_float2(c[j][0], c[j][1]);
        *reinterpret_cast<float2*>(outp + (r0 + 8) * U_DIM + col) = make_float2(c[j][2], c[j][3]);
    }
}

// ---------------- Kernel 2: recurrence + head ----------------
// 128 CTAs, 512 threads. u = tid>>1, parity p = tid&1.
// Thread (u,p) owns k-chunks c = 2i+p (i=0..31), 4 k per chunk, U as 64 bf16x2 regs.
// h double-buffered fp32 in smem; partner-sum via shfl.bfly(1).

static constexpr int RNN_SMEM_BYTES = 2048 + 128;    // h[2][256] + hid[32]

__global__ void __launch_bounds__(512, 1)
rnn_kernel(const float* __restrict__ Um, const float* __restrict__ W1,
           const float* __restrict__ b1, const float* __restrict__ W2,
           const float* __restrict__ b2, float* __restrict__ out) {
    extern __shared__ char smem[];
    float* h   = reinterpret_cast<float*>(smem);
    float* hid = h + 512;
    const int tid = threadIdx.x;
    const int b   = blockIdx.x;
    const int u   = tid >> 1;
    const int p   = tid & 1;

    // --- one-time: U row u, parity-interleaved chunks -> 64 bf16x2 regs ---
    uint32_t ur[64];
    {
        const float4* src = reinterpret_cast<const float4*>(Um + (size_t)u * U_DIM);
        #pragma unroll
        for (int i = 0; i < 32; i++) {
            float4 v = src[2 * i + p];
            ur[2 * i]     = packbf(v.x, v.y);
            ur[2 * i + 1] = packbf(v.z, v.w);
        }
    }
    if (tid < 256) h[tid] = 0.0f;   // buffer 0 = initial state
    __syncthreads();

    const float* xwb = g_xw + (size_t)b * U_DIM + u;

    for (int t = 0; t < T_DIM; t++) {
        float xw = xwb[(size_t)t * (B_DIM * U_DIM)];   // L2 hit, used late
        const float4* hp = reinterpret_cast<const float4*>(h + ((t & 1) << 8)) + p;
        float a0 = 0.f, a1 = 0.f, a2 = 0.f, a3 = 0.f;
        #pragma unroll
        for (int i = 0; i < 32; i++) {
            float4 hv = hp[2 * i];                 // chunk c = 2i+p (16B, bcast pair)
            uint32_t r0 = ur[2 * i], r1 = ur[2 * i + 1];
            a0 = fmaf(blo(r0), hv.x, a0);
            a1 = fmaf(__uint_as_float(r0), hv.y, a1);   // hi bf16, dirty mantissa
            a2 = fmaf(blo(r1), hv.z, a2);
            a3 = fmaf(__uint_as_float(r1), hv.w, a3);
        }
        float s = (a0 + a1) + (a2 + a3);
        s += __shfl_xor_sync(0xffffffffu, s, 1);   // partner (other k-half)
        s += xw;
        float hn;
        asm("tanh.approx.f32 %0, %1;" : "=f"(hn) : "f"(s));
        if (p == 0) h[(((t & 1) ^ 1) << 8) + u] = hn;
        __syncthreads();
    }

    // Head: final h in buffer 0 (t=511 wrote buffer 0)
    const float* hf = h;
    if (tid < 32) {
        float a = b1[tid];
        #pragma unroll 8
        for (int k = 0; k < 256; k++) a += hf[k] * W1[k * 32 + tid];
        hid[tid] = fmaxf(a, 0.0f);
    }
    __syncthreads();
    if (tid == 0) {
        float l0 = b2[0], l1 = b2[1];
        #pragma unroll
        for (int j = 0; j < 32; j++) {
            float x = hid[j];
            l0 += x * W2[j * 2 + 0];
            l1 += x * W2[j * 2 + 1];
        }
        float mx = fmaxf(l0, l1);
        float e0 = __expf(l0 - mx), e1 = __expf(l1 - mx);
        float inv = 1.0f / (e0 + e1);
        out[b * 2 + 0] = e0 * inv;
        out[b * 2 + 1] = e1 * inv;
    }
}

// ---------------- launch ----------------
extern "C" void kernel_launch(void* const* d_in, const int* in_sizes, int n_in,
                              void* d_out, int out_size) {
    const int*   sentence = (const int*)  d_in[0];
    const float* emb      = (const float*)d_in[1];
    const float* W        = (const float*)d_in[2];
    const float* Um       = (const float*)d_in[3];
    const float* W1       = (const float*)d_in[4];
    const float* b1       = (const float*)d_in[5];
    const float* W2       = (const float*)d_in[6];
    const float* b2       = (const float*)d_in[7];
    float* out = (float*)d_out;

    cudaFuncSetAttribute(xw_kernel,  cudaFuncAttributeMaxDynamicSharedMemorySize, XW_SMEM);
    cudaFuncSetAttribute(rnn_kernel, cudaFuncAttributeMaxDynamicSharedMemorySize, RNN_SMEM_BYTES);

    xw_kernel<<<T_DIM, 256, XW_SMEM>>>(sentence, emb, W);
    rnn_kernel<<<B_DIM, 512, RNN_SMEM_BYTES>>>(Um, W1, b1, W2, b2, out);
}